// round 15
// baseline (speedup 1.0000x reference)
#include <cuda_runtime.h>
#include <cuda_bf16.h>
#include <cuda_fp16.h>
#include <stdint.h>

#define N_NODES  100000
#define N_EDGES  1600000
#define IN_C     128
#define HID      128
#define LAT      64
#define N_LAYERS 3
#define N_GRAPHS 1000

#define SCAN_B   512
#define SCAN_NB  ((N_NODES + SCAN_B - 1) / SCAN_B)   // 196

#define AH_STR     136                 // A image bf16 row stride (full K=128, padded)
#define MROWS      256                 // mlp block tile rows
#define AH2_ELEMS  (MROWS * AH_STR)    // 34816 elems per A image
#define WTC_STRIDE 72                  // W image bf16 row stride per 64-K chunk
#define WTC_ELEMS  (128 * WTC_STRIDE)  // 9216

// ---------------- scratch (device globals; no allocation allowed) ----------------
__device__ __align__(16) __half g_h16[N_NODES * HID];                 // fp16 h buffer
__device__ __align__(16) __half g_x16[N_NODES * HID];                 // fp16 copy of x
__device__ __align__(16) __nv_bfloat16 g_aggH[N_NODES * HID];         // split agg (hi)
__device__ __align__(16) __nv_bfloat16 g_aggL[N_NODES * HID];         // split agg (lo)
__device__ __align__(16) float g_pool[N_GRAPHS * HID];
__device__ __align__(16) __nv_bfloat16 g_wt_hi[12 * WTC_ELEMS];       // [mat*2+chunk]
__device__ __align__(16) __nv_bfloat16 g_wt_lo[12 * WTC_ELEMS];
__device__ int   g_deg[N_NODES];
__device__ int   g_rowptr[N_NODES + 1];
__device__ int   g_cursor[N_NODES];
__device__ int   g_col[N_EDGES];
__device__ int   g_bsums[SCAN_NB];
__device__ int   g_is64;   // 1 if indices are int64 on device, 0 if int32

__device__ __forceinline__ int idx_at(const void* p, long long i, int is64) {
    if (is64) return (int)((const long long*)p)[i];
    return ((const int*)p)[i];
}

// packed split-bf16 conversion: (x,y) -> hi pair (x low half) + lo residual pair
__device__ __forceinline__ void split2(float x, float y, uint32_t& uh, uint32_t& ul) {
    asm("cvt.rn.bf16x2.f32 %0, %1, %2;" : "=r"(uh) : "f"(y), "f"(x));
    float hx = __uint_as_float(uh << 16);
    float hy = __uint_as_float(uh & 0xFFFF0000u);
    float lx = x - hx, ly = y - hy;
    asm("cvt.rn.bf16x2.f32 %0, %1, %2;" : "=r"(ul) : "f"(ly), "f"(lx));
}

// ---------------- init: dtype detect + zero deg/pool (one launch) ----------------
__global__ void k_dzero(const void* ei) {
    int i = blockIdx.x * blockDim.x + threadIdx.x;
    if (i == 0) {
        const long long* e64 = (const long long*)ei;
        int ok = 1;
        for (int q = 0; q < 256; q++) {
            long long v = e64[q];
            if (v < 0 || v >= N_NODES) { ok = 0; break; }
        }
        g_is64 = ok;
    }
    if (i < N_NODES) g_deg[i] = 0;
    if (i < N_GRAPHS * HID) g_pool[i] = 0.0f;
}

// ---------------- x -> fp16 copy (one-time per launch) ----------------
__global__ __launch_bounds__(256) void k_x16(const float* __restrict__ x,
                                             __half* __restrict__ out) {
    int i = blockIdx.x * blockDim.x + threadIdx.x;   // one float4 -> one half4
    if (i >= N_NODES * 32) return;
    float4 f = ((const float4*)x)[i];
    uint2 o;
    *(__half2*)&o.x = __floats2half2_rn(f.x, f.y);
    *(__half2*)&o.y = __floats2half2_rn(f.z, f.w);
    ((uint2*)out)[i] = o;
}

__global__ void k_hist(const void* __restrict__ ei) {
    int e = blockIdx.x * blockDim.x + threadIdx.x;
    int is64 = g_is64;
    if (e < N_EDGES) {
        int dst = idx_at(ei, (long long)N_EDGES + e, is64);
        atomicAdd(&g_deg[dst], 1);
    }
}

__global__ void k_scan_local() {
    __shared__ int s[SCAN_B];
    int i = blockIdx.x * SCAN_B + threadIdx.x;
    int v = (i < N_NODES) ? g_deg[i] : 0;
    s[threadIdx.x] = v;
    __syncthreads();
    #pragma unroll
    for (int off = 1; off < SCAN_B; off <<= 1) {
        int t = (threadIdx.x >= off) ? s[threadIdx.x - off] : 0;
        __syncthreads();
        s[threadIdx.x] += t;
        __syncthreads();
    }
    if (i < N_NODES) g_rowptr[i] = s[threadIdx.x] - v;   // exclusive (block-local)
    if (threadIdx.x == SCAN_B - 1) g_bsums[blockIdx.x] = s[threadIdx.x];
}

__global__ void k_scan_add2() {
    __shared__ int pref;
    if (threadIdx.x < 32) {
        int acc = 0;
        for (int b = threadIdx.x; b < blockIdx.x; b += 32) acc += g_bsums[b];
        #pragma unroll
        for (int o = 16; o > 0; o >>= 1) acc += __shfl_down_sync(0xFFFFFFFF, acc, o);
        if (threadIdx.x == 0) pref = acc;
    }
    __syncthreads();
    int i = blockIdx.x * SCAN_B + threadIdx.x;
    if (i < N_NODES) {
        int v = g_rowptr[i] + pref;
        g_rowptr[i] = v;
        g_cursor[i] = v;
    }
    if (i == 0) g_rowptr[N_NODES] = N_EDGES;
}

__global__ void k_scatter(const void* __restrict__ ei) {
    int e = blockIdx.x * blockDim.x + threadIdx.x;
    int is64 = g_is64;
    if (e < N_EDGES) {
        int src = idx_at(ei, e, is64);
        int dst = idx_at(ei, (long long)N_EDGES + e, is64);
        int pos = atomicAdd(&g_cursor[dst], 1);
        g_col[pos] = src;
    }
}

// ---------------- weight prep: W^T + bf16 split into chunked padded images ------
__global__ void k_wprep(const float* __restrict__ W1, const float* __restrict__ W2) {
    int idx = blockIdx.x * blockDim.x + threadIdx.x;
    if (idx >= 6 * 16384) return;
    int mat = idx >> 14;
    int rem = idx & 16383;
    int n = rem >> 7;         // output col = B row
    int k = rem & 127;        // global K index
    int l = mat >> 1;
    const float* W = (mat & 1) ? W2 : W1;
    float v = W[l * 16384 + k * 128 + n];
    __nv_bfloat16 hi = __float2bfloat16_rn(v);
    __nv_bfloat16 lo = __float2bfloat16_rn(v - __bfloat162float(hi));
    int chunk = k >> 6, kl = k & 63;
    int off = (mat * 2 + chunk) * WTC_ELEMS + n * WTC_STRIDE + kl;
    g_wt_hi[off] = hi;
    g_wt_lo[off] = lo;
}

// ---------------- aggregation (fp16 input, all layers): half the gather bytes ----
__device__ __forceinline__ void add_h4(float4& a, uint2 v) {
    float2 p0 = __half22float2(*(const __half2*)&v.x);
    float2 p1 = __half22float2(*(const __half2*)&v.y);
    a.x += p0.x; a.y += p0.y; a.z += p1.x; a.w += p1.y;
}

__global__ __launch_bounds__(256) void k_agg16(const __half* __restrict__ h,
                                               __nv_bfloat16* __restrict__ outH,
                                               __nv_bfloat16* __restrict__ outL) {
    int warp = (blockIdx.x * blockDim.x + threadIdx.x) >> 5;
    int lane = threadIdx.x & 31;
    if (warp >= N_NODES) return;
    const uint2* h2 = (const uint2*)h;   // 4 halves per uint2; row = 32 uint2
    float4 acc = make_float4(0.f, 0.f, 0.f, 0.f);
    add_h4(acc, h2[(size_t)warp * 32 + lane]);
    int s = g_rowptr[warp];
    int e = g_rowptr[warp + 1];
    int j = s;
    for (; j + 7 < e; j += 8) {
        int c0 = g_col[j + 0], c1 = g_col[j + 1], c2 = g_col[j + 2], c3 = g_col[j + 3];
        int c4 = g_col[j + 4], c5 = g_col[j + 5], c6 = g_col[j + 6], c7 = g_col[j + 7];
        uint2 v0 = h2[(size_t)c0 * 32 + lane];
        uint2 v1 = h2[(size_t)c1 * 32 + lane];
        uint2 v2 = h2[(size_t)c2 * 32 + lane];
        uint2 v3 = h2[(size_t)c3 * 32 + lane];
        uint2 v4 = h2[(size_t)c4 * 32 + lane];
        uint2 v5 = h2[(size_t)c5 * 32 + lane];
        uint2 v6 = h2[(size_t)c6 * 32 + lane];
        uint2 v7 = h2[(size_t)c7 * 32 + lane];
        add_h4(acc, v0); add_h4(acc, v1); add_h4(acc, v2); add_h4(acc, v3);
        add_h4(acc, v4); add_h4(acc, v5); add_h4(acc, v6); add_h4(acc, v7);
    }
    for (; j < e; j++) {
        add_h4(acc, h2[(size_t)g_col[j] * 32 + lane]);
    }
    uint2 uh, ul;
    split2(acc.x, acc.y, uh.x, ul.x);
    split2(acc.z, acc.w, uh.y, ul.y);
    size_t off = (size_t)warp * 128 + lane * 4;
    *(uint2*)(outH + off) = uh;
    *(uint2*)(outL + off) = ul;
}

// ---------------- MMA helpers ----------------------------------------------------
__device__ __forceinline__ void mma16816(float* d, const uint32_t* a, const uint32_t* b) {
    asm volatile(
        "mma.sync.aligned.m16n8k16.row.col.f32.bf16.bf16.f32 "
        "{%0,%1,%2,%3}, {%4,%5,%6,%7}, {%8,%9}, {%0,%1,%2,%3};"
        : "+f"(d[0]), "+f"(d[1]), "+f"(d[2]), "+f"(d[3])
        : "r"(a[0]), "r"(a[1]), "r"(a[2]), "r"(a[3]), "r"(b[0]), "r"(b[1]));
}

__device__ __forceinline__ void copy_w(int img, __nv_bfloat16* WtH, __nv_bfloat16* WtL, int tid) {
    const uint4* gwh = (const uint4*)(g_wt_hi + img * WTC_ELEMS);
    const uint4* gwl = (const uint4*)(g_wt_lo + img * WTC_ELEMS);
    uint4* swh = (uint4*)WtH;
    uint4* swl = (uint4*)WtL;
    #pragma unroll
    for (int i = 0; i < 5; i++) {
        int idx = tid + i * 256;
        if (idx < WTC_ELEMS / 8) { swh[idx] = gwh[idx]; swl[idx] = gwl[idx]; }
    }
}

// one 64-K chunk of split-bf16 3-pass MMA; warp tile 64x64 (4 m-atoms x 8 n-atoms)
__device__ __forceinline__ void mma_chunk(const __nv_bfloat16* AsH, const __nv_bfloat16* AsL,
                                          const __nv_bfloat16* WtH, const __nv_bfloat16* WtL,
                                          float acc[4][8][4], int aRow0, int bN0,
                                          int chunk, int tig) {
    #pragma unroll
    for (int pass = 0; pass < 3; pass++) {
        const __nv_bfloat16* Ab = (pass == 2) ? AsL : AsH;   // AhWh, AhWl, AlWh
        const __nv_bfloat16* Wb = (pass == 1) ? WtL : WtH;
        #pragma unroll
        for (int ks = 0; ks < 4; ks++) {
            int kA = chunk * 64 + ks * 16 + tig * 2;
            int kW = ks * 16 + tig * 2;
            uint32_t afr[4][4];
            #pragma unroll
            for (int am = 0; am < 4; am++) {
                const __nv_bfloat16* base = Ab + (aRow0 + am * 16) * AH_STR + kA;
                afr[am][0] = *(const uint32_t*)(base);
                afr[am][1] = *(const uint32_t*)(base + 8 * AH_STR);
                afr[am][2] = *(const uint32_t*)(base + 8);
                afr[am][3] = *(const uint32_t*)(base + 8 * AH_STR + 8);
            }
            uint32_t bfr[8][2];
            #pragma unroll
            for (int an = 0; an < 8; an++) {
                const __nv_bfloat16* bb = Wb + (bN0 + an * 8) * WTC_STRIDE + kW;
                bfr[an][0] = *(const uint32_t*)(bb);
                bfr[an][1] = *(const uint32_t*)(bb + 8);
            }
            #pragma unroll
            for (int am = 0; am < 4; am++)
                #pragma unroll
                for (int an = 0; an < 8; an++)
                    mma16816(acc[am][an], afr[am], bfr[an]);
        }
    }
}

// ---------------- fused MLP: relu(relu(A@W1+b1)@W2+b2) (-> pool) -----------------
// 256 rows/block, 256 threads (8 warps: 4 m-groups x 2 n-groups, warp tile 64x64).
// smem: A_hi/A_lo [256][136] + W_hi/W_lo chunk [128][72] = 176128 B. 1 block/SM.
// Output h is stored fp16 (half2) when do_pool==0.
__global__ __launch_bounds__(256) void k_mlp(const __nv_bfloat16* __restrict__ AHg,
                                             const __nv_bfloat16* __restrict__ ALg,
                                             int l,
                                             const float* __restrict__ b1,
                                             const float* __restrict__ b2,
                                             __half* __restrict__ Hout,
                                             const void* __restrict__ batch,
                                             int do_pool) {
    extern __shared__ __nv_bfloat16 sm[];
    __nv_bfloat16* AsH = sm;
    __nv_bfloat16* AsL = sm + AH2_ELEMS;
    __nv_bfloat16* WtH = sm + 2 * AH2_ELEMS;
    __nv_bfloat16* WtL = sm + 2 * AH2_ELEMS + WTC_ELEMS;
    int tid = threadIdx.x;
    int lane = tid & 31, wid = tid >> 5;
    int rowBase = blockIdx.x * MROWS;
    int warpM = wid >> 1, warpN = wid & 1;
    int g = lane >> 2, tig = lane & 3;
    const int aRow0 = warpM * 64 + g;
    const int bN0   = warpN * 64 + g;

    copy_w(4 * l + 0, WtH, WtL, tid);

    // copy pre-split A (256 rows x 128 K, hi+lo): 16 uint4 per row per image
    {
        #pragma unroll
        for (int i = 0; i < 16; i++) {
            int idx = tid + i * 256;        // 0..4095
            int r = idx >> 4;               // 0..255
            int q = idx & 15;               // uint4 within row
            int grow = rowBase + r;
            uint4 vh = make_uint4(0, 0, 0, 0), vl = make_uint4(0, 0, 0, 0);
            if (grow < N_NODES) {
                vh = *(const uint4*)(AHg + (size_t)grow * 128 + q * 8);
                vl = *(const uint4*)(ALg + (size_t)grow * 128 + q * 8);
            }
            *(uint4*)(AsH + r * AH_STR + q * 8) = vh;
            *(uint4*)(AsL + r * AH_STR + q * 8) = vl;
        }
    }
    __syncthreads();

    float acc[4][8][4];
    #pragma unroll
    for (int am = 0; am < 4; am++)
        #pragma unroll
        for (int an = 0; an < 8; an++)
            #pragma unroll
            for (int q = 0; q < 4; q++) acc[am][an][q] = 0.0f;

    // ---- MLP1: A @ W1 ----
    mma_chunk(AsH, AsL, WtH, WtL, acc, aRow0, bN0, 0, tig);
    __syncthreads();
    copy_w(4 * l + 1, WtH, WtL, tid);
    __syncthreads();
    mma_chunk(AsH, AsL, WtH, WtL, acc, aRow0, bN0, 1, tig);
    __syncthreads();   // all A-image reads done before overwrite

    // ---- relu(C1 + b1) -> back into A images; stage W2 chunk0 ----
    {
        float bv0[8], bv1[8];
        #pragma unroll
        for (int an = 0; an < 8; an++) {
            int col = warpN * 64 + an * 8 + tig * 2;
            bv0[an] = __ldg(&b1[col]);
            bv1[an] = __ldg(&b1[col + 1]);
        }
        #pragma unroll
        for (int am = 0; am < 4; am++) {
            int r0 = warpM * 64 + am * 16 + g;
            int r1 = r0 + 8;
            #pragma unroll
            for (int an = 0; an < 8; an++) {
                int c = warpN * 64 + an * 8 + tig * 2;
                float v00 = fmaxf(acc[am][an][0] + bv0[an], 0.0f);
                float v01 = fmaxf(acc[am][an][1] + bv1[an], 0.0f);
                float v10 = fmaxf(acc[am][an][2] + bv0[an], 0.0f);
                float v11 = fmaxf(acc[am][an][3] + bv1[an], 0.0f);
                uint32_t uh0, ul0, uh1, ul1;
                split2(v00, v01, uh0, ul0);
                split2(v10, v11, uh1, ul1);
                *(uint32_t*)(AsH + r0 * AH_STR + c) = uh0;
                *(uint32_t*)(AsL + r0 * AH_STR + c) = ul0;
                *(uint32_t*)(AsH + r1 * AH_STR + c) = uh1;
                *(uint32_t*)(AsL + r1 * AH_STR + c) = ul1;
            }
        }
        copy_w(4 * l + 2, WtH, WtL, tid);
        #pragma unroll
        for (int am = 0; am < 4; am++)
            #pragma unroll
            for (int an = 0; an < 8; an++)
                #pragma unroll
                for (int q = 0; q < 4; q++) acc[am][an][q] = 0.0f;
    }
    __syncthreads();

    // ---- MLP2: A @ W2 ----
    mma_chunk(AsH, AsL, WtH, WtL, acc, aRow0, bN0, 0, tig);
    __syncthreads();
    copy_w(4 * l + 3, WtH, WtL, tid);
    __syncthreads();
    mma_chunk(AsH, AsL, WtH, WtL, acc, aRow0, bN0, 1, tig);

    // ---- epilogue: relu(C2 + b2) -> Hout (fp16), or fused pool atomics ----
    float bv0[8], bv1[8];
    #pragma unroll
    for (int an = 0; an < 8; an++) {
        int col = warpN * 64 + an * 8 + tig * 2;
        bv0[an] = __ldg(&b2[col]);
        bv1[an] = __ldg(&b2[col + 1]);
    }
    if (!do_pool) {
        #pragma unroll
        for (int an = 0; an < 8; an++) {
            int col = warpN * 64 + an * 8 + tig * 2;
            #pragma unroll
            for (int am = 0; am < 4; am++) {
                int row0 = rowBase + warpM * 64 + am * 16 + g;
                if (row0 < N_NODES) {
                    __half2 o = __floats2half2_rn(
                        fmaxf(acc[am][an][0] + bv0[an], 0.0f),
                        fmaxf(acc[am][an][1] + bv1[an], 0.0f));
                    *(__half2*)&Hout[(size_t)row0 * 128 + col] = o;
                }
                int row1 = row0 + 8;
                if (row1 < N_NODES) {
                    __half2 o = __floats2half2_rn(
                        fmaxf(acc[am][an][2] + bv0[an], 0.0f),
                        fmaxf(acc[am][an][3] + bv1[an], 0.0f));
                    *(__half2*)&Hout[(size_t)row1 * 128 + col] = o;
                }
            }
        }
    } else {
        int is64 = g_is64;
        #pragma unroll
        for (int am = 0; am < 4; am++) {
            int row0 = rowBase + warpM * 64 + am * 16 + g;
            int row1 = row0 + 8;
            int g0 = (row0 < N_NODES) ? idx_at(batch, row0, is64) : -1;
            int g1 = (row1 < N_NODES) ? idx_at(batch, row1, is64) : -1;
            #pragma unroll
            for (int an = 0; an < 8; an++) {
                int col = warpN * 64 + an * 8 + tig * 2;
                if (g0 >= 0) {
                    atomicAdd(&g_pool[(size_t)g0 * 128 + col],     fmaxf(acc[am][an][0] + bv0[an], 0.0f));
                    atomicAdd(&g_pool[(size_t)g0 * 128 + col + 1], fmaxf(acc[am][an][1] + bv1[an], 0.0f));
                }
                if (g1 >= 0) {
                    atomicAdd(&g_pool[(size_t)g1 * 128 + col],     fmaxf(acc[am][an][2] + bv0[an], 0.0f));
                    atomicAdd(&g_pool[(size_t)g1 * 128 + col + 1], fmaxf(acc[am][an][3] + bv1[an], 0.0f));
                }
            }
        }
    }
}

// ---------------- head: mu = g@W_mu+b_mu, lv = g@W_lv+b_lv ----------------
__global__ __launch_bounds__(128) void k_head(const float* __restrict__ Wmu,
                                              const float* __restrict__ bmu,
                                              const float* __restrict__ Wlv,
                                              const float* __restrict__ blv,
                                              float* __restrict__ out) {
    __shared__ float p[128];
    int g = blockIdx.x;
    p[threadIdx.x] = g_pool[(size_t)g * 128 + threadIdx.x];
    __syncthreads();
    int t = threadIdx.x;
    const float* W = (t < 64) ? Wmu : Wlv;
    const float* b = (t < 64) ? bmu : blv;
    int c = t & 63;
    float acc = 0.0f;
    #pragma unroll 8
    for (int k = 0; k < 128; k++) acc += p[k] * W[k * 64 + c];
    acc += b[c];
    size_t off = (t < 64) ? 0 : (size_t)N_GRAPHS * LAT;
    out[off + (size_t)g * 64 + c] = acc;
}

// ---------------- launch ----------------
extern "C" void kernel_launch(void* const* d_in, const int* in_sizes, int n_in,
                              void* d_out, int out_size) {
    const float* x    = (const float*)d_in[0];
    const void*  ei   = d_in[1];           // int32 or int64; detected in-graph
    const void*  bat  = d_in[2];
    const float* W1   = (const float*)d_in[3];
    const float* b1   = (const float*)d_in[4];
    const float* W2   = (const float*)d_in[5];
    const float* b2   = (const float*)d_in[6];
    const float* Wmu  = (const float*)d_in[7];
    const float* bmu  = (const float*)d_in[8];
    const float* Wlv  = (const float*)d_in[9];
    const float* blv  = (const float*)d_in[10];
    float*       out  = (float*)d_out;

    __half *h16, *x16;
    __nv_bfloat16 *aggH, *aggL;
    cudaGetSymbolAddress((void**)&h16, g_h16);
    cudaGetSymbolAddress((void**)&x16, g_x16);
    cudaGetSymbolAddress((void**)&aggH, g_aggH);
    cudaGetSymbolAddress((void**)&aggL, g_aggL);

    const int M_SMEM = (2 * AH2_ELEMS + 2 * WTC_ELEMS) * (int)sizeof(__nv_bfloat16); // 176128
    cudaFuncSetAttribute(k_mlp, cudaFuncAttributeMaxDynamicSharedMemorySize, M_SMEM);

    // init + CSR build + x conversion (per-launch; replay-safe)
    k_dzero<<<(N_GRAPHS * HID + 255) / 256, 256>>>(ei);
    k_x16<<<(N_NODES * 32 + 255) / 256, 256>>>(x, x16);
    k_hist<<<(N_EDGES + 255) / 256, 256>>>(ei);
    k_scan_local<<<SCAN_NB, SCAN_B>>>();
    k_scan_add2<<<SCAN_NB, SCAN_B>>>();
    k_scatter<<<(N_EDGES + 255) / 256, 256>>>(ei);

    const int aggGrid = (N_NODES * 32 + 255) / 256;    // warp per node
    const int mGrid   = (N_NODES + MROWS - 1) / MROWS; // 391

    // layer 0 (gathers fp16 x)
    k_agg16<<<aggGrid, 256>>>(x16, aggH, aggL);
    k_wprep<<<(6 * 16384 + 255) / 256, 256>>>(W1, W2);
    k_mlp<<<mGrid, 256, M_SMEM>>>(aggH, aggL, 0, b1 + 0 * 128, b2 + 0 * 128, h16, bat, 0);
    // layer 1 (gathers fp16 h)
    k_agg16<<<aggGrid, 256>>>(h16, aggH, aggL);
    k_mlp<<<mGrid, 256, M_SMEM>>>(aggH, aggL, 1, b1 + 1 * 128, b2 + 1 * 128, h16, bat, 0);
    // layer 2 (gathers fp16 h; fused pool)
    k_agg16<<<aggGrid, 256>>>(h16, aggH, aggL);
    k_mlp<<<mGrid, 256, M_SMEM>>>(aggH, aggL, 2, b1 + 2 * 128, b2 + 2 * 128, h16, bat, 1);

    // heads
    k_head<<<N_GRAPHS, 128>>>(Wmu, bmu, Wlv, blv, out);
}

// round 16
// speedup vs baseline: 1.0479x; 1.0479x over previous
#include <cuda_runtime.h>
#include <cuda_bf16.h>
#include <cuda_fp16.h>
#include <stdint.h>

#define N_NODES  100000
#define N_EDGES  1600000
#define IN_C     128
#define HID      128
#define LAT      64
#define N_LAYERS 3
#define N_GRAPHS 1000

#define SCAN_B   512
#define SCAN_NB  ((N_NODES + SCAN_B - 1) / SCAN_B)   // 196

#define AH_STR     136                 // A image bf16 row stride (full K=128, padded)
#define MROWS      256                 // mlp block tile rows
#define AH2_ELEMS  (MROWS * AH_STR)    // 34816 elems per A image
#define WTC_STRIDE 72                  // W image bf16 row stride per 64-K chunk
#define WTC_ELEMS  (128 * WTC_STRIDE)  // 9216

// ---------------- scratch (device globals; no allocation allowed) ----------------
__device__ __align__(16) __half g_h16[N_NODES * HID];                 // fp16 h buffer
__device__ __align__(16) __half g_x16[N_NODES * HID];                 // fp16 copy of x
__device__ __align__(16) __half g_agg16[N_NODES * HID];               // fp16 agg output
__device__ __align__(16) float g_pool[N_GRAPHS * HID];
__device__ __align__(16) __nv_bfloat16 g_wt_hi[12 * WTC_ELEMS];       // [mat*2+chunk]
__device__ __align__(16) __nv_bfloat16 g_wt_lo[12 * WTC_ELEMS];
__device__ int   g_deg[N_NODES];
__device__ int   g_rowptr[N_NODES + 1];
__device__ int   g_cursor[N_NODES];
__device__ int   g_col[N_EDGES];
__device__ int   g_bsums[SCAN_NB];
__device__ int   g_is64;   // 1 if indices are int64 on device, 0 if int32

__device__ __forceinline__ int idx_at(const void* p, long long i, int is64) {
    if (is64) return (int)((const long long*)p)[i];
    return ((const int*)p)[i];
}

// packed split-bf16 conversion: (x,y) -> hi pair (x low half) + lo residual pair
__device__ __forceinline__ void split2(float x, float y, uint32_t& uh, uint32_t& ul) {
    asm("cvt.rn.bf16x2.f32 %0, %1, %2;" : "=r"(uh) : "f"(y), "f"(x));
    float hx = __uint_as_float(uh << 16);
    float hy = __uint_as_float(uh & 0xFFFF0000u);
    float lx = x - hx, ly = y - hy;
    asm("cvt.rn.bf16x2.f32 %0, %1, %2;" : "=r"(ul) : "f"(ly), "f"(lx));
}

// ---------------- init: dtype detect + zero deg/pool + x->fp16 (one launch) ------
__global__ __launch_bounds__(256) void k_init(const void* ei, const float* __restrict__ x,
                                              __half* __restrict__ x16) {
    int i = blockIdx.x * blockDim.x + threadIdx.x;
    if (i == 0) {
        const long long* e64 = (const long long*)ei;
        int ok = 1;
        for (int q = 0; q < 256; q++) {
            long long v = e64[q];
            if (v < 0 || v >= N_NODES) { ok = 0; break; }
        }
        g_is64 = ok;
    }
    if (i < N_NODES) g_deg[i] = 0;
    if (i < N_GRAPHS * HID) g_pool[i] = 0.0f;
    if (i < N_NODES * 32) {
        float4 f = ((const float4*)x)[i];
        uint2 o;
        *(__half2*)&o.x = __floats2half2_rn(f.x, f.y);
        *(__half2*)&o.y = __floats2half2_rn(f.z, f.w);
        ((uint2*)x16)[i] = o;
    }
}

__global__ void k_hist(const void* __restrict__ ei) {
    int e = blockIdx.x * blockDim.x + threadIdx.x;
    int is64 = g_is64;
    if (e < N_EDGES) {
        int dst = idx_at(ei, (long long)N_EDGES + e, is64);
        atomicAdd(&g_deg[dst], 1);
    }
}

__global__ void k_scan_local() {
    __shared__ int s[SCAN_B];
    int i = blockIdx.x * SCAN_B + threadIdx.x;
    int v = (i < N_NODES) ? g_deg[i] : 0;
    s[threadIdx.x] = v;
    __syncthreads();
    #pragma unroll
    for (int off = 1; off < SCAN_B; off <<= 1) {
        int t = (threadIdx.x >= off) ? s[threadIdx.x - off] : 0;
        __syncthreads();
        s[threadIdx.x] += t;
        __syncthreads();
    }
    if (i < N_NODES) g_rowptr[i] = s[threadIdx.x] - v;   // exclusive (block-local)
    if (threadIdx.x == SCAN_B - 1) g_bsums[blockIdx.x] = s[threadIdx.x];
}

__global__ void k_scan_add2() {
    __shared__ int pref;
    if (threadIdx.x < 32) {
        int acc = 0;
        for (int b = threadIdx.x; b < blockIdx.x; b += 32) acc += g_bsums[b];
        #pragma unroll
        for (int o = 16; o > 0; o >>= 1) acc += __shfl_down_sync(0xFFFFFFFF, acc, o);
        if (threadIdx.x == 0) pref = acc;
    }
    __syncthreads();
    int i = blockIdx.x * SCAN_B + threadIdx.x;
    if (i < N_NODES) {
        int v = g_rowptr[i] + pref;
        g_rowptr[i] = v;
        g_cursor[i] = v;
    }
    if (i == 0) g_rowptr[N_NODES] = N_EDGES;
}

__global__ void k_scatter(const void* __restrict__ ei) {
    int e = blockIdx.x * blockDim.x + threadIdx.x;
    int is64 = g_is64;
    if (e < N_EDGES) {
        int src = idx_at(ei, e, is64);
        int dst = idx_at(ei, (long long)N_EDGES + e, is64);
        int pos = atomicAdd(&g_cursor[dst], 1);
        g_col[pos] = src;
    }
}

// ---------------- weight prep: W^T + bf16 split into chunked padded images ------
__global__ void k_wprep(const float* __restrict__ W1, const float* __restrict__ W2) {
    int idx = blockIdx.x * blockDim.x + threadIdx.x;
    if (idx >= 6 * 16384) return;
    int mat = idx >> 14;
    int rem = idx & 16383;
    int n = rem >> 7;         // output col = B row
    int k = rem & 127;        // global K index
    int l = mat >> 1;
    const float* W = (mat & 1) ? W2 : W1;
    float v = W[l * 16384 + k * 128 + n];
    __nv_bfloat16 hi = __float2bfloat16_rn(v);
    __nv_bfloat16 lo = __float2bfloat16_rn(v - __bfloat162float(hi));
    int chunk = k >> 6, kl = k & 63;
    int off = (mat * 2 + chunk) * WTC_ELEMS + n * WTC_STRIDE + kl;
    g_wt_hi[off] = hi;
    g_wt_lo[off] = lo;
}

// ---------------- aggregation (fp16 in/out): agg[n] = h[n] + sum CSR -------------
__device__ __forceinline__ void add_h4(float4& a, uint2 v) {
    float2 p0 = __half22float2(*(const __half2*)&v.x);
    float2 p1 = __half22float2(*(const __half2*)&v.y);
    a.x += p0.x; a.y += p0.y; a.z += p1.x; a.w += p1.y;
}

__global__ __launch_bounds__(256) void k_agg16(const __half* __restrict__ h,
                                               __half* __restrict__ outA) {
    int warp = (blockIdx.x * blockDim.x + threadIdx.x) >> 5;
    int lane = threadIdx.x & 31;
    if (warp >= N_NODES) return;
    const uint2* h2 = (const uint2*)h;   // 4 halves per uint2; row = 32 uint2
    float4 acc = make_float4(0.f, 0.f, 0.f, 0.f);
    add_h4(acc, h2[(size_t)warp * 32 + lane]);
    int s = g_rowptr[warp];
    int e = g_rowptr[warp + 1];
    int j = s;
    for (; j + 7 < e; j += 8) {
        int c0 = g_col[j + 0], c1 = g_col[j + 1], c2 = g_col[j + 2], c3 = g_col[j + 3];
        int c4 = g_col[j + 4], c5 = g_col[j + 5], c6 = g_col[j + 6], c7 = g_col[j + 7];
        uint2 v0 = h2[(size_t)c0 * 32 + lane];
        uint2 v1 = h2[(size_t)c1 * 32 + lane];
        uint2 v2 = h2[(size_t)c2 * 32 + lane];
        uint2 v3 = h2[(size_t)c3 * 32 + lane];
        uint2 v4 = h2[(size_t)c4 * 32 + lane];
        uint2 v5 = h2[(size_t)c5 * 32 + lane];
        uint2 v6 = h2[(size_t)c6 * 32 + lane];
        uint2 v7 = h2[(size_t)c7 * 32 + lane];
        add_h4(acc, v0); add_h4(acc, v1); add_h4(acc, v2); add_h4(acc, v3);
        add_h4(acc, v4); add_h4(acc, v5); add_h4(acc, v6); add_h4(acc, v7);
    }
    for (; j < e; j++) {
        add_h4(acc, h2[(size_t)g_col[j] * 32 + lane]);
    }
    uint2 o;
    *(__half2*)&o.x = __floats2half2_rn(acc.x, acc.y);
    *(__half2*)&o.y = __floats2half2_rn(acc.z, acc.w);
    ((uint2*)outA)[(size_t)warp * 32 + lane] = o;
}

// ---------------- MMA helpers ----------------------------------------------------
__device__ __forceinline__ void mma16816(float* d, const uint32_t* a, const uint32_t* b) {
    asm volatile(
        "mma.sync.aligned.m16n8k16.row.col.f32.bf16.bf16.f32 "
        "{%0,%1,%2,%3}, {%4,%5,%6,%7}, {%8,%9}, {%0,%1,%2,%3};"
        : "+f"(d[0]), "+f"(d[1]), "+f"(d[2]), "+f"(d[3])
        : "r"(a[0]), "r"(a[1]), "r"(a[2]), "r"(a[3]), "r"(b[0]), "r"(b[1]));
}

__device__ __forceinline__ void copy_w(int img, __nv_bfloat16* WtH, __nv_bfloat16* WtL, int tid) {
    const uint4* gwh = (const uint4*)(g_wt_hi + img * WTC_ELEMS);
    const uint4* gwl = (const uint4*)(g_wt_lo + img * WTC_ELEMS);
    uint4* swh = (uint4*)WtH;
    uint4* swl = (uint4*)WtL;
    #pragma unroll
    for (int i = 0; i < 5; i++) {
        int idx = tid + i * 256;
        if (idx < WTC_ELEMS / 8) { swh[idx] = gwh[idx]; swl[idx] = gwl[idx]; }
    }
}

// one 64-K chunk of split-bf16 3-pass MMA; warp tile 64x64 (4 m-atoms x 8 n-atoms)
__device__ __forceinline__ void mma_chunk(const __nv_bfloat16* AsH, const __nv_bfloat16* AsL,
                                          const __nv_bfloat16* WtH, const __nv_bfloat16* WtL,
                                          float acc[4][8][4], int aRow0, int bN0,
                                          int chunk, int tig) {
    #pragma unroll
    for (int pass = 0; pass < 3; pass++) {
        const __nv_bfloat16* Ab = (pass == 2) ? AsL : AsH;   // AhWh, AhWl, AlWh
        const __nv_bfloat16* Wb = (pass == 1) ? WtL : WtH;
        #pragma unroll
        for (int ks = 0; ks < 4; ks++) {
            int kA = chunk * 64 + ks * 16 + tig * 2;
            int kW = ks * 16 + tig * 2;
            uint32_t afr[4][4];
            #pragma unroll
            for (int am = 0; am < 4; am++) {
                const __nv_bfloat16* base = Ab + (aRow0 + am * 16) * AH_STR + kA;
                afr[am][0] = *(const uint32_t*)(base);
                afr[am][1] = *(const uint32_t*)(base + 8 * AH_STR);
                afr[am][2] = *(const uint32_t*)(base + 8);
                afr[am][3] = *(const uint32_t*)(base + 8 * AH_STR + 8);
            }
            uint32_t bfr[8][2];
            #pragma unroll
            for (int an = 0; an < 8; an++) {
                const __nv_bfloat16* bb = Wb + (bN0 + an * 8) * WTC_STRIDE + kW;
                bfr[an][0] = *(const uint32_t*)(bb);
                bfr[an][1] = *(const uint32_t*)(bb + 8);
            }
            #pragma unroll
            for (int am = 0; am < 4; am++)
                #pragma unroll
                for (int an = 0; an < 8; an++)
                    mma16816(acc[am][an], afr[am], bfr[an]);
        }
    }
}

// ---------------- fused MLP: relu(relu(A@W1+b1)@W2+b2) (-> pool) -----------------
// 256 rows/block, 256 threads (8 warps: 4 m-groups x 2 n-groups, warp tile 64x64).
// A arrives as fp16; copy phase splits to bf16 hi/lo images in smem.
// smem: A_hi/A_lo [256][136] + W_hi/W_lo chunk [128][72] = 176128 B. 1 block/SM.
__global__ __launch_bounds__(256) void k_mlp(const __half* __restrict__ Ag,
                                             int l,
                                             const float* __restrict__ b1,
                                             const float* __restrict__ b2,
                                             __half* __restrict__ Hout,
                                             const void* __restrict__ batch,
                                             int do_pool) {
    extern __shared__ __nv_bfloat16 sm[];
    __nv_bfloat16* AsH = sm;
    __nv_bfloat16* AsL = sm + AH2_ELEMS;
    __nv_bfloat16* WtH = sm + 2 * AH2_ELEMS;
    __nv_bfloat16* WtL = sm + 2 * AH2_ELEMS + WTC_ELEMS;
    int tid = threadIdx.x;
    int lane = tid & 31, wid = tid >> 5;
    int rowBase = blockIdx.x * MROWS;
    int warpM = wid >> 1, warpN = wid & 1;
    int g = lane >> 2, tig = lane & 3;
    const int aRow0 = warpM * 64 + g;
    const int bN0   = warpN * 64 + g;

    copy_w(4 * l + 0, WtH, WtL, tid);

    // load fp16 A (256 rows x 128 K = 16 uint4/row), split-convert to bf16 images
    {
        const uint4* a4 = (const uint4*)Ag;   // 8 halves per uint4
        #pragma unroll
        for (int i = 0; i < 16; i++) {
            int idx = tid + i * 256;        // 0..4095
            int r = idx >> 4;               // 0..255
            int q = idx & 15;               // uint4 within row
            int grow = rowBase + r;
            uint4 v = make_uint4(0, 0, 0, 0);
            if (grow < N_NODES) v = a4[(size_t)grow * 16 + q];
            uint4 vh, vl;
            float2 f0 = __half22float2(*(const __half2*)&v.x);
            float2 f1 = __half22float2(*(const __half2*)&v.y);
            float2 f2 = __half22float2(*(const __half2*)&v.z);
            float2 f3 = __half22float2(*(const __half2*)&v.w);
            split2(f0.x, f0.y, vh.x, vl.x);
            split2(f1.x, f1.y, vh.y, vl.y);
            split2(f2.x, f2.y, vh.z, vl.z);
            split2(f3.x, f3.y, vh.w, vl.w);
            *(uint4*)(AsH + r * AH_STR + q * 8) = vh;
            *(uint4*)(AsL + r * AH_STR + q * 8) = vl;
        }
    }
    __syncthreads();

    float acc[4][8][4];
    #pragma unroll
    for (int am = 0; am < 4; am++)
        #pragma unroll
        for (int an = 0; an < 8; an++)
            #pragma unroll
            for (int q = 0; q < 4; q++) acc[am][an][q] = 0.0f;

    // ---- MLP1: A @ W1 ----
    mma_chunk(AsH, AsL, WtH, WtL, acc, aRow0, bN0, 0, tig);
    __syncthreads();
    copy_w(4 * l + 1, WtH, WtL, tid);
    __syncthreads();
    mma_chunk(AsH, AsL, WtH, WtL, acc, aRow0, bN0, 1, tig);
    __syncthreads();   // all A-image reads done before overwrite

    // ---- relu(C1 + b1) -> back into A images; stage W2 chunk0 ----
    {
        float bv0[8], bv1[8];
        #pragma unroll
        for (int an = 0; an < 8; an++) {
            int col = warpN * 64 + an * 8 + tig * 2;
            bv0[an] = __ldg(&b1[col]);
            bv1[an] = __ldg(&b1[col + 1]);
        }
        #pragma unroll
        for (int am = 0; am < 4; am++) {
            int r0 = warpM * 64 + am * 16 + g;
            int r1 = r0 + 8;
            #pragma unroll
            for (int an = 0; an < 8; an++) {
                int c = warpN * 64 + an * 8 + tig * 2;
                float v00 = fmaxf(acc[am][an][0] + bv0[an], 0.0f);
                float v01 = fmaxf(acc[am][an][1] + bv1[an], 0.0f);
                float v10 = fmaxf(acc[am][an][2] + bv0[an], 0.0f);
                float v11 = fmaxf(acc[am][an][3] + bv1[an], 0.0f);
                uint32_t uh0, ul0, uh1, ul1;
                split2(v00, v01, uh0, ul0);
                split2(v10, v11, uh1, ul1);
                *(uint32_t*)(AsH + r0 * AH_STR + c) = uh0;
                *(uint32_t*)(AsL + r0 * AH_STR + c) = ul0;
                *(uint32_t*)(AsH + r1 * AH_STR + c) = uh1;
                *(uint32_t*)(AsL + r1 * AH_STR + c) = ul1;
            }
        }
        copy_w(4 * l + 2, WtH, WtL, tid);
        #pragma unroll
        for (int am = 0; am < 4; am++)
            #pragma unroll
            for (int an = 0; an < 8; an++)
                #pragma unroll
                for (int q = 0; q < 4; q++) acc[am][an][q] = 0.0f;
    }
    __syncthreads();

    // ---- MLP2: A @ W2 ----
    mma_chunk(AsH, AsL, WtH, WtL, acc, aRow0, bN0, 0, tig);
    __syncthreads();
    copy_w(4 * l + 3, WtH, WtL, tid);
    __syncthreads();
    mma_chunk(AsH, AsL, WtH, WtL, acc, aRow0, bN0, 1, tig);

    // ---- epilogue: relu(C2 + b2) -> Hout (fp16), or fused pool atomics ----
    float bv0[8], bv1[8];
    #pragma unroll
    for (int an = 0; an < 8; an++) {
        int col = warpN * 64 + an * 8 + tig * 2;
        bv0[an] = __ldg(&b2[col]);
        bv1[an] = __ldg(&b2[col + 1]);
    }
    if (!do_pool) {
        #pragma unroll
        for (int an = 0; an < 8; an++) {
            int col = warpN * 64 + an * 8 + tig * 2;
            #pragma unroll
            for (int am = 0; am < 4; am++) {
                int row0 = rowBase + warpM * 64 + am * 16 + g;
                if (row0 < N_NODES) {
                    __half2 o = __floats2half2_rn(
                        fmaxf(acc[am][an][0] + bv0[an], 0.0f),
                        fmaxf(acc[am][an][1] + bv1[an], 0.0f));
                    *(__half2*)&Hout[(size_t)row0 * 128 + col] = o;
                }
                int row1 = row0 + 8;
                if (row1 < N_NODES) {
                    __half2 o = __floats2half2_rn(
                        fmaxf(acc[am][an][2] + bv0[an], 0.0f),
                        fmaxf(acc[am][an][3] + bv1[an], 0.0f));
                    *(__half2*)&Hout[(size_t)row1 * 128 + col] = o;
                }
            }
        }
    } else {
        int is64 = g_is64;
        #pragma unroll
        for (int am = 0; am < 4; am++) {
            int row0 = rowBase + warpM * 64 + am * 16 + g;
            int row1 = row0 + 8;
            int g0 = (row0 < N_NODES) ? idx_at(batch, row0, is64) : -1;
            int g1 = (row1 < N_NODES) ? idx_at(batch, row1, is64) : -1;
            #pragma unroll
            for (int an = 0; an < 8; an++) {
                int col = warpN * 64 + an * 8 + tig * 2;
                if (g0 >= 0) {
                    atomicAdd(&g_pool[(size_t)g0 * 128 + col],     fmaxf(acc[am][an][0] + bv0[an], 0.0f));
                    atomicAdd(&g_pool[(size_t)g0 * 128 + col + 1], fmaxf(acc[am][an][1] + bv1[an], 0.0f));
                }
                if (g1 >= 0) {
                    atomicAdd(&g_pool[(size_t)g1 * 128 + col],     fmaxf(acc[am][an][2] + bv0[an], 0.0f));
                    atomicAdd(&g_pool[(size_t)g1 * 128 + col + 1], fmaxf(acc[am][an][3] + bv1[an], 0.0f));
                }
            }
        }
    }
}

// ---------------- head: mu = g@W_mu+b_mu, lv = g@W_lv+b_lv ----------------
__global__ __launch_bounds__(128) void k_head(const float* __restrict__ Wmu,
                                              const float* __restrict__ bmu,
                                              const float* __restrict__ Wlv,
                                              const float* __restrict__ blv,
                                              float* __restrict__ out) {
    __shared__ float p[128];
    int g = blockIdx.x;
    p[threadIdx.x] = g_pool[(size_t)g * 128 + threadIdx.x];
    __syncthreads();
    int t = threadIdx.x;
    const float* W = (t < 64) ? Wmu : Wlv;
    const float* b = (t < 64) ? bmu : blv;
    int c = t & 63;
    float acc = 0.0f;
    #pragma unroll 8
    for (int k = 0; k < 128; k++) acc += p[k] * W[k * 64 + c];
    acc += b[c];
    size_t off = (t < 64) ? 0 : (size_t)N_GRAPHS * LAT;
    out[off + (size_t)g * 64 + c] = acc;
}

// ---------------- launch ----------------
extern "C" void kernel_launch(void* const* d_in, const int* in_sizes, int n_in,
                              void* d_out, int out_size) {
    const float* x    = (const float*)d_in[0];
    const void*  ei   = d_in[1];           // int32 or int64; detected in-graph
    const void*  bat  = d_in[2];
    const float* W1   = (const float*)d_in[3];
    const float* b1   = (const float*)d_in[4];
    const float* W2   = (const float*)d_in[5];
    const float* b2   = (const float*)d_in[6];
    const float* Wmu  = (const float*)d_in[7];
    const float* bmu  = (const float*)d_in[8];
    const float* Wlv  = (const float*)d_in[9];
    const float* blv  = (const float*)d_in[10];
    float*       out  = (float*)d_out;

    __half *h16, *x16, *agg16;
    cudaGetSymbolAddress((void**)&h16, g_h16);
    cudaGetSymbolAddress((void**)&x16, g_x16);
    cudaGetSymbolAddress((void**)&agg16, g_agg16);

    const int M_SMEM = (2 * AH2_ELEMS + 2 * WTC_ELEMS) * (int)sizeof(__nv_bfloat16); // 176128
    cudaFuncSetAttribute(k_mlp, cudaFuncAttributeMaxDynamicSharedMemorySize, M_SMEM);

    // init (detect + zero + x conversion) + CSR build (per-launch; replay-safe)
    k_init<<<(N_NODES * 32 + 255) / 256, 256>>>(ei, x, x16);
    k_hist<<<(N_EDGES + 255) / 256, 256>>>(ei);
    k_scan_local<<<SCAN_NB, SCAN_B>>>();
    k_scan_add2<<<SCAN_NB, SCAN_B>>>();
    k_scatter<<<(N_EDGES + 255) / 256, 256>>>(ei);

    const int aggGrid = (N_NODES * 32 + 255) / 256;    // warp per node
    const int mGrid   = (N_NODES + MROWS - 1) / MROWS; // 391

    // layer 0 (agg is 6th launch -> ncu -s 5 -c 1 captures it)
    k_agg16<<<aggGrid, 256>>>(x16, agg16);
    k_wprep<<<(6 * 16384 + 255) / 256, 256>>>(W1, W2);
    k_mlp<<<mGrid, 256, M_SMEM>>>(agg16, 0, b1 + 0 * 128, b2 + 0 * 128, h16, bat, 0);
    // layer 1
    k_agg16<<<aggGrid, 256>>>(h16, agg16);
    k_mlp<<<mGrid, 256, M_SMEM>>>(agg16, 1, b1 + 1 * 128, b2 + 1 * 128, h16, bat, 0);
    // layer 2 (fused pool)
    k_agg16<<<aggGrid, 256>>>(h16, agg16);
    k_mlp<<<mGrid, 256, M_SMEM>>>(agg16, 2, b1 + 2 * 128, b2 + 2 * 128, h16, bat, 1);

    // heads
    k_head<<<N_GRAPHS, 128>>>(Wmu, bmu, Wlv, blv, out);
}

// round 17
// speedup vs baseline: 1.2218x; 1.1660x over previous
#include <cuda_runtime.h>
#include <cuda_bf16.h>
#include <cuda_fp16.h>
#include <stdint.h>

#define N_NODES  100000
#define N_EDGES  1600000
#define IN_C     128
#define HID      128
#define LAT      64
#define N_LAYERS 3
#define N_GRAPHS 1000

#define SCAN_B   512
#define SCAN_NB  ((N_NODES + SCAN_B - 1) / SCAN_B)   // 196

#define AH_STR     136                 // A image fp16 row stride (full K=128, padded)
#define MROWS      256                 // mlp block tile rows
#define AH2_ELEMS  (MROWS * AH_STR)    // 34816 halves per A image
#define WTC_STRIDE 72                  // W image fp16 row stride per 64-K chunk
#define WTC_ELEMS  (128 * WTC_STRIDE)  // 9216

// ---------------- scratch (device globals; no allocation allowed) ----------------
__device__ __align__(16) __half g_h16[N_NODES * HID];                 // fp16 h buffer
__device__ __align__(16) __half g_x16[N_NODES * HID];                 // fp16 copy of x
__device__ __align__(16) __half g_agg16[N_NODES * HID];               // fp16 agg output
__device__ __align__(16) float g_pool[N_GRAPHS * HID];
__device__ __align__(16) __half g_wt_hi[12 * WTC_ELEMS];              // [mat*2+chunk]
__device__ __align__(16) __half g_wt_lo[12 * WTC_ELEMS];
__device__ int   g_deg[N_NODES];
__device__ int   g_rowptr[N_NODES + 1];
__device__ int   g_cursor[N_NODES];
__device__ int   g_col[N_EDGES];
__device__ int   g_bsums[SCAN_NB];
__device__ int   g_is64;   // 1 if indices are int64 on device, 0 if int32

__device__ __forceinline__ int idx_at(const void* p, long long i, int is64) {
    if (is64) return (int)((const long long*)p)[i];
    return ((const int*)p)[i];
}

// ---------------- init: dtype detect + zero deg/pool + x->fp16 (one launch) ------
__global__ __launch_bounds__(256) void k_init(const void* ei, const float* __restrict__ x,
                                              __half* __restrict__ x16) {
    int i = blockIdx.x * blockDim.x + threadIdx.x;
    if (i == 0) {
        const long long* e64 = (const long long*)ei;
        int ok = 1;
        for (int q = 0; q < 256; q++) {
            long long v = e64[q];
            if (v < 0 || v >= N_NODES) { ok = 0; break; }
        }
        g_is64 = ok;
    }
    if (i < N_NODES) g_deg[i] = 0;
    if (i < N_GRAPHS * HID) g_pool[i] = 0.0f;
    if (i < N_NODES * 32) {
        float4 f = ((const float4*)x)[i];
        uint2 o;
        *(__half2*)&o.x = __floats2half2_rn(f.x, f.y);
        *(__half2*)&o.y = __floats2half2_rn(f.z, f.w);
        ((uint2*)x16)[i] = o;
    }
}

__global__ void k_hist(const void* __restrict__ ei) {
    int e = blockIdx.x * blockDim.x + threadIdx.x;
    int is64 = g_is64;
    if (e < N_EDGES) {
        int dst = idx_at(ei, (long long)N_EDGES + e, is64);
        atomicAdd(&g_deg[dst], 1);
    }
}

__global__ void k_scan_local() {
    __shared__ int s[SCAN_B];
    int i = blockIdx.x * SCAN_B + threadIdx.x;
    int v = (i < N_NODES) ? g_deg[i] : 0;
    s[threadIdx.x] = v;
    __syncthreads();
    #pragma unroll
    for (int off = 1; off < SCAN_B; off <<= 1) {
        int t = (threadIdx.x >= off) ? s[threadIdx.x - off] : 0;
        __syncthreads();
        s[threadIdx.x] += t;
        __syncthreads();
    }
    if (i < N_NODES) g_rowptr[i] = s[threadIdx.x] - v;   // exclusive (block-local)
    if (threadIdx.x == SCAN_B - 1) g_bsums[blockIdx.x] = s[threadIdx.x];
}

__global__ void k_scan_add2() {
    __shared__ int pref;
    if (threadIdx.x < 32) {
        int acc = 0;
        for (int b = threadIdx.x; b < blockIdx.x; b += 32) acc += g_bsums[b];
        #pragma unroll
        for (int o = 16; o > 0; o >>= 1) acc += __shfl_down_sync(0xFFFFFFFF, acc, o);
        if (threadIdx.x == 0) pref = acc;
    }
    __syncthreads();
    int i = blockIdx.x * SCAN_B + threadIdx.x;
    if (i < N_NODES) {
        int v = g_rowptr[i] + pref;
        g_rowptr[i] = v;
        g_cursor[i] = v;
    }
    if (i == 0) g_rowptr[N_NODES] = N_EDGES;
}

__global__ void k_scatter(const void* __restrict__ ei) {
    int e = blockIdx.x * blockDim.x + threadIdx.x;
    int is64 = g_is64;
    if (e < N_EDGES) {
        int src = idx_at(ei, e, is64);
        int dst = idx_at(ei, (long long)N_EDGES + e, is64);
        int pos = atomicAdd(&g_cursor[dst], 1);
        g_col[pos] = src;
    }
}

// ---------------- weight prep: W^T + fp16 split into chunked padded images ------
__global__ void k_wprep(const float* __restrict__ W1, const float* __restrict__ W2) {
    int idx = blockIdx.x * blockDim.x + threadIdx.x;
    if (idx >= 6 * 16384) return;
    int mat = idx >> 14;
    int rem = idx & 16383;
    int n = rem >> 7;         // output col = B row
    int k = rem & 127;        // global K index
    int l = mat >> 1;
    const float* W = (mat & 1) ? W2 : W1;
    float v = W[l * 16384 + k * 128 + n];
    __half hi = __float2half_rn(v);
    __half lo = __float2half_rn(v - __half2float(hi));
    int chunk = k >> 6, kl = k & 63;
    int off = (mat * 2 + chunk) * WTC_ELEMS + n * WTC_STRIDE + kl;
    g_wt_hi[off] = hi;
    g_wt_lo[off] = lo;
}

// ---------------- aggregation (fp16 in/out): agg[n] = h[n] + sum CSR -------------
__device__ __forceinline__ void add_h4(float4& a, uint2 v) {
    float2 p0 = __half22float2(*(const __half2*)&v.x);
    float2 p1 = __half22float2(*(const __half2*)&v.y);
    a.x += p0.x; a.y += p0.y; a.z += p1.x; a.w += p1.y;
}

__global__ __launch_bounds__(256) void k_agg16(const __half* __restrict__ h,
                                               __half* __restrict__ outA) {
    int warp = (blockIdx.x * blockDim.x + threadIdx.x) >> 5;
    int lane = threadIdx.x & 31;
    if (warp >= N_NODES) return;
    const uint2* h2 = (const uint2*)h;   // 4 halves per uint2; row = 32 uint2
    float4 acc = make_float4(0.f, 0.f, 0.f, 0.f);
    add_h4(acc, h2[(size_t)warp * 32 + lane]);
    int s = g_rowptr[warp];
    int e = g_rowptr[warp + 1];
    int j = s;
    for (; j + 7 < e; j += 8) {
        int c0 = g_col[j + 0], c1 = g_col[j + 1], c2 = g_col[j + 2], c3 = g_col[j + 3];
        int c4 = g_col[j + 4], c5 = g_col[j + 5], c6 = g_col[j + 6], c7 = g_col[j + 7];
        uint2 v0 = h2[(size_t)c0 * 32 + lane];
        uint2 v1 = h2[(size_t)c1 * 32 + lane];
        uint2 v2 = h2[(size_t)c2 * 32 + lane];
        uint2 v3 = h2[(size_t)c3 * 32 + lane];
        uint2 v4 = h2[(size_t)c4 * 32 + lane];
        uint2 v5 = h2[(size_t)c5 * 32 + lane];
        uint2 v6 = h2[(size_t)c6 * 32 + lane];
        uint2 v7 = h2[(size_t)c7 * 32 + lane];
        add_h4(acc, v0); add_h4(acc, v1); add_h4(acc, v2); add_h4(acc, v3);
        add_h4(acc, v4); add_h4(acc, v5); add_h4(acc, v6); add_h4(acc, v7);
    }
    for (; j < e; j++) {
        add_h4(acc, h2[(size_t)g_col[j] * 32 + lane]);
    }
    uint2 o;
    *(__half2*)&o.x = __floats2half2_rn(acc.x, acc.y);
    *(__half2*)&o.y = __floats2half2_rn(acc.z, acc.w);
    ((uint2*)outA)[(size_t)warp * 32 + lane] = o;
}

// ---------------- MMA helpers (fp16 operands, fp32 accumulate) -------------------
__device__ __forceinline__ void mma16816h(float* d, const uint32_t* a, const uint32_t* b) {
    asm volatile(
        "mma.sync.aligned.m16n8k16.row.col.f32.f16.f16.f32 "
        "{%0,%1,%2,%3}, {%4,%5,%6,%7}, {%8,%9}, {%0,%1,%2,%3};"
        : "+f"(d[0]), "+f"(d[1]), "+f"(d[2]), "+f"(d[3])
        : "r"(a[0]), "r"(a[1]), "r"(a[2]), "r"(a[3]), "r"(b[0]), "r"(b[1]));
}

__device__ __forceinline__ void copy_w(int img, __half* WtH, __half* WtL, int tid) {
    const uint4* gwh = (const uint4*)(g_wt_hi + img * WTC_ELEMS);
    const uint4* gwl = (const uint4*)(g_wt_lo + img * WTC_ELEMS);
    uint4* swh = (uint4*)WtH;
    uint4* swl = (uint4*)WtL;
    #pragma unroll
    for (int i = 0; i < 5; i++) {
        int idx = tid + i * 256;
        if (idx < WTC_ELEMS / 8) { swh[idx] = gwh[idx]; swl[idx] = gwl[idx]; }
    }
}

// one 64-K chunk: A(fp16 exact) x (Wh + Wl), 2 passes sharing A fragments
__device__ __forceinline__ void mma_chunk(const __half* As,
                                          const __half* WtH, const __half* WtL,
                                          float acc[4][8][4], int aRow0, int bN0,
                                          int chunk, int tig) {
    #pragma unroll
    for (int ks = 0; ks < 4; ks++) {
        int kA = chunk * 64 + ks * 16 + tig * 2;
        int kW = ks * 16 + tig * 2;
        uint32_t afr[4][4];
        #pragma unroll
        for (int am = 0; am < 4; am++) {
            const __half* base = As + (aRow0 + am * 16) * AH_STR + kA;
            afr[am][0] = *(const uint32_t*)(base);
            afr[am][1] = *(const uint32_t*)(base + 8 * AH_STR);
            afr[am][2] = *(const uint32_t*)(base + 8);
            afr[am][3] = *(const uint32_t*)(base + 8 * AH_STR + 8);
        }
        uint32_t bh[8][2], bl[8][2];
        #pragma unroll
        for (int an = 0; an < 8; an++) {
            const __half* bbh = WtH + (bN0 + an * 8) * WTC_STRIDE + kW;
            const __half* bbl = WtL + (bN0 + an * 8) * WTC_STRIDE + kW;
            bh[an][0] = *(const uint32_t*)(bbh);
            bh[an][1] = *(const uint32_t*)(bbh + 8);
            bl[an][0] = *(const uint32_t*)(bbl);
            bl[an][1] = *(const uint32_t*)(bbl + 8);
        }
        #pragma unroll
        for (int am = 0; am < 4; am++)
            #pragma unroll
            for (int an = 0; an < 8; an++)
                mma16816h(acc[am][an], afr[am], bh[an]);
        #pragma unroll
        for (int am = 0; am < 4; am++)
            #pragma unroll
            for (int an = 0; an < 8; an++)
                mma16816h(acc[am][an], afr[am], bl[an]);
    }
}

// ---------------- fused MLP: relu(relu(A@W1+b1)@W2+b2) (-> pool) -----------------
// 256 rows/block, 256 threads (8 warps: 4 m-groups x 2 n-groups, warp tile 64x64).
// A is fp16 (exact MMA operand); only W is split (fp16 hi/lo, ~2^-21 precision).
// smem: A [256][136] fp16 + W hi/lo chunk [128][72] fp16 = 106496 B.
__global__ __launch_bounds__(256) void k_mlp(const __half* __restrict__ Ag,
                                             int l,
                                             const float* __restrict__ b1,
                                             const float* __restrict__ b2,
                                             __half* __restrict__ Hout,
                                             const void* __restrict__ batch,
                                             int do_pool) {
    extern __shared__ __half smh[];
    __half* As  = smh;
    __half* WtH = smh + AH2_ELEMS;
    __half* WtL = smh + AH2_ELEMS + WTC_ELEMS;
    int tid = threadIdx.x;
    int lane = tid & 31, wid = tid >> 5;
    int rowBase = blockIdx.x * MROWS;
    int warpM = wid >> 1, warpN = wid & 1;
    int g = lane >> 2, tig = lane & 3;
    const int aRow0 = warpM * 64 + g;
    const int bN0   = warpN * 64 + g;

    copy_w(4 * l + 0, WtH, WtL, tid);

    // pure copy of fp16 A (256 rows x 128 K = 16 uint4/row)
    {
        const uint4* a4 = (const uint4*)Ag;   // 8 halves per uint4
        #pragma unroll
        for (int i = 0; i < 16; i++) {
            int idx = tid + i * 256;        // 0..4095
            int r = idx >> 4;               // 0..255
            int q = idx & 15;               // uint4 within row
            int grow = rowBase + r;
            uint4 v = make_uint4(0, 0, 0, 0);
            if (grow < N_NODES) v = a4[(size_t)grow * 16 + q];
            *(uint4*)(As + r * AH_STR + q * 8) = v;
        }
    }
    __syncthreads();

    float acc[4][8][4];
    #pragma unroll
    for (int am = 0; am < 4; am++)
        #pragma unroll
        for (int an = 0; an < 8; an++)
            #pragma unroll
            for (int q = 0; q < 4; q++) acc[am][an][q] = 0.0f;

    // ---- MLP1: A @ W1 ----
    mma_chunk(As, WtH, WtL, acc, aRow0, bN0, 0, tig);
    __syncthreads();
    copy_w(4 * l + 1, WtH, WtL, tid);
    __syncthreads();
    mma_chunk(As, WtH, WtL, acc, aRow0, bN0, 1, tig);
    __syncthreads();   // all A reads done before overwrite

    // ---- relu(C1 + b1) -> back into A image (fp16); stage W2 chunk0 ----
    {
        float bv0[8], bv1[8];
        #pragma unroll
        for (int an = 0; an < 8; an++) {
            int col = warpN * 64 + an * 8 + tig * 2;
            bv0[an] = __ldg(&b1[col]);
            bv1[an] = __ldg(&b1[col + 1]);
        }
        #pragma unroll
        for (int am = 0; am < 4; am++) {
            int r0 = warpM * 64 + am * 16 + g;
            int r1 = r0 + 8;
            #pragma unroll
            for (int an = 0; an < 8; an++) {
                int c = warpN * 64 + an * 8 + tig * 2;
                __half2 h0 = __floats2half2_rn(
                    fmaxf(acc[am][an][0] + bv0[an], 0.0f),
                    fmaxf(acc[am][an][1] + bv1[an], 0.0f));
                __half2 h1 = __floats2half2_rn(
                    fmaxf(acc[am][an][2] + bv0[an], 0.0f),
                    fmaxf(acc[am][an][3] + bv1[an], 0.0f));
                *(__half2*)(As + r0 * AH_STR + c) = h0;
                *(__half2*)(As + r1 * AH_STR + c) = h1;
            }
        }
        copy_w(4 * l + 2, WtH, WtL, tid);
        #pragma unroll
        for (int am = 0; am < 4; am++)
            #pragma unroll
            for (int an = 0; an < 8; an++)
                #pragma unroll
                for (int q = 0; q < 4; q++) acc[am][an][q] = 0.0f;
    }
    __syncthreads();

    // ---- MLP2: A @ W2 ----
    mma_chunk(As, WtH, WtL, acc, aRow0, bN0, 0, tig);
    __syncthreads();
    copy_w(4 * l + 3, WtH, WtL, tid);
    __syncthreads();
    mma_chunk(As, WtH, WtL, acc, aRow0, bN0, 1, tig);

    // ---- epilogue: relu(C2 + b2) -> Hout (fp16), or fused pool atomics ----
    float bv0[8], bv1[8];
    #pragma unroll
    for (int an = 0; an < 8; an++) {
        int col = warpN * 64 + an * 8 + tig * 2;
        bv0[an] = __ldg(&b2[col]);
        bv1[an] = __ldg(&b2[col + 1]);
    }
    if (!do_pool) {
        #pragma unroll
        for (int an = 0; an < 8; an++) {
            int col = warpN * 64 + an * 8 + tig * 2;
            #pragma unroll
            for (int am = 0; am < 4; am++) {
                int row0 = rowBase + warpM * 64 + am * 16 + g;
                if (row0 < N_NODES) {
                    __half2 o = __floats2half2_rn(
                        fmaxf(acc[am][an][0] + bv0[an], 0.0f),
                        fmaxf(acc[am][an][1] + bv1[an], 0.0f));
                    *(__half2*)&Hout[(size_t)row0 * 128 + col] = o;
                }
                int row1 = row0 + 8;
                if (row1 < N_NODES) {
                    __half2 o = __floats2half2_rn(
                        fmaxf(acc[am][an][2] + bv0[an], 0.0f),
                        fmaxf(acc[am][an][3] + bv1[an], 0.0f));
                    *(__half2*)&Hout[(size_t)row1 * 128 + col] = o;
                }
            }
        }
    } else {
        int is64 = g_is64;
        #pragma unroll
        for (int am = 0; am < 4; am++) {
            int row0 = rowBase + warpM * 64 + am * 16 + g;
            int row1 = row0 + 8;
            int g0 = (row0 < N_NODES) ? idx_at(batch, row0, is64) : -1;
            int g1 = (row1 < N_NODES) ? idx_at(batch, row1, is64) : -1;
            #pragma unroll
            for (int an = 0; an < 8; an++) {
                int col = warpN * 64 + an * 8 + tig * 2;
                if (g0 >= 0) {
                    atomicAdd(&g_pool[(size_t)g0 * 128 + col],     fmaxf(acc[am][an][0] + bv0[an], 0.0f));
                    atomicAdd(&g_pool[(size_t)g0 * 128 + col + 1], fmaxf(acc[am][an][1] + bv1[an], 0.0f));
                }
                if (g1 >= 0) {
                    atomicAdd(&g_pool[(size_t)g1 * 128 + col],     fmaxf(acc[am][an][2] + bv0[an], 0.0f));
                    atomicAdd(&g_pool[(size_t)g1 * 128 + col + 1], fmaxf(acc[am][an][3] + bv1[an], 0.0f));
                }
            }
        }
    }
}

// ---------------- head: mu = g@W_mu+b_mu, lv = g@W_lv+b_lv ----------------
__global__ __launch_bounds__(128) void k_head(const float* __restrict__ Wmu,
                                              const float* __restrict__ bmu,
                                              const float* __restrict__ Wlv,
                                              const float* __restrict__ blv,
                                              float* __restrict__ out) {
    __shared__ float p[128];
    int g = blockIdx.x;
    p[threadIdx.x] = g_pool[(size_t)g * 128 + threadIdx.x];
    __syncthreads();
    int t = threadIdx.x;
    const float* W = (t < 64) ? Wmu : Wlv;
    const float* b = (t < 64) ? bmu : blv;
    int c = t & 63;
    float acc = 0.0f;
    #pragma unroll 8
    for (int k = 0; k < 128; k++) acc += p[k] * W[k * 64 + c];
    acc += b[c];
    size_t off = (t < 64) ? 0 : (size_t)N_GRAPHS * LAT;
    out[off + (size_t)g * 64 + c] = acc;
}

// ---------------- launch ----------------
extern "C" void kernel_launch(void* const* d_in, const int* in_sizes, int n_in,
                              void* d_out, int out_size) {
    const float* x    = (const float*)d_in[0];
    const void*  ei   = d_in[1];           // int32 or int64; detected in-graph
    const void*  bat  = d_in[2];
    const float* W1   = (const float*)d_in[3];
    const float* b1   = (const float*)d_in[4];
    const float* W2   = (const float*)d_in[5];
    const float* b2   = (const float*)d_in[6];
    const float* Wmu  = (const float*)d_in[7];
    const float* bmu  = (const float*)d_in[8];
    const float* Wlv  = (const float*)d_in[9];
    const float* blv  = (const float*)d_in[10];
    float*       out  = (float*)d_out;

    __half *h16, *x16, *agg16;
    cudaGetSymbolAddress((void**)&h16, g_h16);
    cudaGetSymbolAddress((void**)&x16, g_x16);
    cudaGetSymbolAddress((void**)&agg16, g_agg16);

    const int M_SMEM = (AH2_ELEMS + 2 * WTC_ELEMS) * (int)sizeof(__half); // 106496
    cudaFuncSetAttribute(k_mlp, cudaFuncAttributeMaxDynamicSharedMemorySize, M_SMEM);

    // init (detect + zero + x conversion) + CSR build (per-launch; replay-safe)
    k_init<<<(N_NODES * 32 + 255) / 256, 256>>>(ei, x, x16);
    k_hist<<<(N_EDGES + 255) / 256, 256>>>(ei);
    k_scan_local<<<SCAN_NB, SCAN_B>>>();
    k_scan_add2<<<SCAN_NB, SCAN_B>>>();
    k_scatter<<<(N_EDGES + 255) / 256, 256>>>(ei);

    const int aggGrid = (N_NODES * 32 + 255) / 256;    // warp per node
    const int mGrid   = (N_NODES + MROWS - 1) / MROWS; // 391

    // layer 0
    k_agg16<<<aggGrid, 256>>>(x16, agg16);
    k_wprep<<<(6 * 16384 + 255) / 256, 256>>>(W1, W2);
    k_mlp<<<mGrid, 256, M_SMEM>>>(agg16, 0, b1 + 0 * 128, b2 + 0 * 128, h16, bat, 0);
    // layer 1
    k_agg16<<<aggGrid, 256>>>(h16, agg16);
    k_mlp<<<mGrid, 256, M_SMEM>>>(agg16, 1, b1 + 1 * 128, b2 + 1 * 128, h16, bat, 0);
    // layer 2 (fused pool)
    k_agg16<<<aggGrid, 256>>>(h16, agg16);
    k_mlp<<<mGrid, 256, M_SMEM>>>(agg16, 2, b1 + 2 * 128, b2 + 2 * 128, h16, bat, 1);

    // heads
    k_head<<<N_GRAPHS, 128>>>(Wmu, bmu, Wlv, blv, out);
}